// round 9
// baseline (speedup 1.0000x reference)
#include <cuda_runtime.h>
#include <cuda_bf16.h>
#include <cstdint>

// Problem constants
#define BATCH 32
#define C     512
#define P     196
#define D     8192
#define DMASK (D - 1)

#define TB    64           // tile block (c1 and c2)
#define KPAD  208          // 13 * 16
#define LDW   108          // row stride in u32 words
#define LDWB  (LDW * 4)    // row stride in bytes (432)
#define NTHREADS 512

// Sketch hash/sign tables extracted from the dense S matrices each launch.
__device__ int   g_h1[C];
__device__ int   g_h2[C];
__device__ float g_s1[C];
__device__ float g_s2[C];

// ---------------------------------------------------------------------------
// Kernel 1: extract (h, s) from dense sketch matrices + zero the output.
// grid: (512, 2)  block: 256
// ---------------------------------------------------------------------------
__global__ void cbp_prep(const float* __restrict__ S1, const float* __restrict__ S2,
                         float* __restrict__ out) {
    const int row = blockIdx.x;
    const float4* r = (const float4*)(((blockIdx.y == 0) ? S1 : S2) + (size_t)row * D);
    for (int j4 = threadIdx.x; j4 < D / 4; j4 += blockDim.x) {
        float4 v = r[j4];
        float nz = 0.0f; int off = 0;
        if (v.x != 0.0f) { nz = v.x; off = 0; }
        if (v.y != 0.0f) { nz = v.y; off = 1; }
        if (v.z != 0.0f) { nz = v.z; off = 2; }
        if (v.w != 0.0f) { nz = v.w; off = 3; }
        if (nz != 0.0f) {
            int j = j4 * 4 + off;
            if (blockIdx.y == 0) { g_h1[row] = j; g_s1[row] = nz; }
            else                 { g_h2[row] = j; g_s2[row] = nz; }
        }
    }
    int base = (blockIdx.y * gridDim.x + blockIdx.x) * 256;
    out[base + threadIdx.x] = 0.0f;
}

// ---------------------------------------------------------------------------
// bf16 error-compensated split helpers
// ---------------------------------------------------------------------------
__device__ __forceinline__ void split2(float x0, float x1,
                                       uint32_t& hi, uint32_t& lo) {
    __nv_bfloat16 h0 = __float2bfloat16(x0);
    __nv_bfloat16 h1 = __float2bfloat16(x1);
    __nv_bfloat16 l0 = __float2bfloat16(x0 - __bfloat162float(h0));
    __nv_bfloat16 l1 = __float2bfloat16(x1 - __bfloat162float(h1));
    __nv_bfloat162 hp = __halves2bfloat162(h0, h1);
    __nv_bfloat162 lp = __halves2bfloat162(l0, l1);
    hi = *(uint32_t*)&hp;
    lo = *(uint32_t*)&lp;
}

__device__ __forceinline__ void cvt_store(uint32_t* Hrow, uint32_t* Lrow,
                                          int j4, float4 v, float s) {
    uint32_t h0, l0, h1, l1;
    split2(v.x * s, v.y * s, h0, l0);
    split2(v.z * s, v.w * s, h1, l1);
    *(uint2*)(Hrow + 2 * j4) = make_uint2(h0, h1);
    *(uint2*)(Lrow + 2 * j4) = make_uint2(l0, l1);
}

__device__ __forceinline__ void mma_bf16(float c[4], const uint32_t a[4],
                                         uint32_t b0, uint32_t b1) {
    asm volatile(
        "mma.sync.aligned.m16n8k16.row.col.f32.bf16.bf16.f32 "
        "{%0,%1,%2,%3}, {%4,%5,%6,%7}, {%8,%9}, {%0,%1,%2,%3};"
        : "+f"(c[0]), "+f"(c[1]), "+f"(c[2]), "+f"(c[3])
        : "r"(a[0]), "r"(a[1]), "r"(a[2]), "r"(a[3]), "r"(b0), "r"(b1));
}

__device__ __forceinline__ void ldsm4(uint32_t r[4], uint32_t addr) {
    asm volatile(
        "ldmatrix.sync.aligned.m8n8.x4.shared.b16 {%0,%1,%2,%3}, [%4];"
        : "=r"(r[0]), "=r"(r[1]), "=r"(r[2]), "=r"(r[3]) : "r"(addr));
}

// ---------------------------------------------------------------------------
// Kernel 2: one 64x64 Gram tile per CTA; HMMA bf16 3-split + REDG scatter.
// grid: (8, 8, 32) = (c1blk, c2blk, batch) = 2048 CTAs.
// 512 threads = 16 warps, 4(m) x 4(n): warp tile 16 rows x 16 cols.
// smem 110,592 B -> 2 CTAs/SM -> 32 warps/SM; ~7 waves of short CTAs whose
// stage/MMA/scatter phases interleave across co-resident CTAs.
// ---------------------------------------------------------------------------
#define SMEM_BYTES (TB * LDW * 4 * 4)

__global__ void __launch_bounds__(NTHREADS, 2)
cbp_main(const float* __restrict__ B1g, const float* __restrict__ B2g,
         float* __restrict__ out) {
    extern __shared__ uint32_t sm4[];
    uint32_t* AH = sm4;                       // [64][LDW]
    uint32_t* AL = AH + TB * LDW;
    uint32_t* BH = AL + TB * LDW;             // [64][LDW]
    uint32_t* BL = BH + TB * LDW;

    const int tid  = threadIdx.x;
    const int wid  = tid >> 5;
    const int lane = tid & 31;
    const int g    = lane >> 2;
    const int tg   = lane & 3;
    const int wm   = wid >> 2;                // 0..3 (16-row strip)
    const int wn   = wid & 3;                 // 0..3 (16-col strip)
    const int b     = blockIdx.z;
    const int c1blk = blockIdx.x * TB;
    const int c2blk = blockIdx.y * TB;

    // ---- Stage both tiles (64 x 208 bf16 hi/lo), sign-folded, zero-padded ----
    {
        const float* Ag = B1g + ((size_t)b * C + c1blk) * P;
        const float* Bg = B2g + ((size_t)b * C + c2blk) * P;
        for (int idx = tid; idx < TB * 52; idx += NTHREADS) {
            int row = idx / 52;
            int j4  = idx % 52;
            float4 va = make_float4(0.f, 0.f, 0.f, 0.f);
            float4 vb = make_float4(0.f, 0.f, 0.f, 0.f);
            if (4 * j4 < P) {
                va = *(const float4*)(Ag + (size_t)row * P + 4 * j4);
                vb = *(const float4*)(Bg + (size_t)row * P + 4 * j4);
            }
            cvt_store(AH + row * LDW, AL + row * LDW, j4, va, g_s1[c1blk + row]);
            cvt_store(BH + row * LDW, BL + row * LDW, j4, vb, g_s2[c2blk + row]);
        }
    }

    // ---- ldmatrix per-lane addresses ----
    const uint32_t AHs = (uint32_t)__cvta_generic_to_shared(AH);
    const uint32_t ALs = (uint32_t)__cvta_generic_to_shared(AL);
    const uint32_t BHs = (uint32_t)__cvta_generic_to_shared(BH);
    const uint32_t BLs = (uint32_t)__cvta_generic_to_shared(BL);
    const int t  = lane >> 3;                 // tile index 0..3
    const int rr = lane & 7;
    const uint32_t aoff = (uint32_t)(wm * 16 + (t & 1) * 8 + rr) * LDWB + (t >> 1) * 16;
    const uint32_t boff = (uint32_t)(wn * 16 + (t >> 1) * 8 + rr) * LDWB + (t & 1) * 16;
    const uint32_t aHa = AHs + aoff, aLa = ALs + aoff;
    const uint32_t bHa = BHs + boff, bLa = BLs + boff;

    __syncthreads();

    // ---- 64x64 tile: warp 16x16, ldmatrix + mma, 3-split accumulation ----
    float cfr[2][4];
    #pragma unroll
    for (int nt = 0; nt < 2; nt++)
        #pragma unroll
        for (int q = 0; q < 4; q++) cfr[nt][q] = 0.0f;

    #pragma unroll
    for (int ks = 0; ks < KPAD / 16; ks++) {
        const uint32_t kb = ks * 32;          // 16 bf16 = 32 bytes per k-step
        uint32_t ah[4], al[4], bh[4], bl[4];
        ldsm4(ah, aHa + kb);
        ldsm4(al, aLa + kb);
        ldsm4(bh, bHa + kb);
        ldsm4(bl, bLa + kb);
        #pragma unroll
        for (int nt = 0; nt < 2; nt++) {
            mma_bf16(cfr[nt], ah, bh[2 * nt], bh[2 * nt + 1]);  // hi*hi
            mma_bf16(cfr[nt], ah, bl[2 * nt], bl[2 * nt + 1]);  // hi*lo
            mma_bf16(cfr[nt], al, bh[2 * nt], bh[2 * nt + 1]);  // lo*hi
        }
    }

    // ---- Scatter C fragments to global bins (fire-and-forget RED.add) ----
    float* outb = out + (size_t)b * D;
    const int r0 = wm * 16 + g;
    const int h1a = g_h1[c1blk + r0];
    const int h1b = g_h1[c1blk + r0 + 8];
    #pragma unroll
    for (int nt = 0; nt < 2; nt++) {
        int cb = c2blk + wn * 16 + nt * 8 + 2 * tg;
        int h2a = g_h2[cb];
        int h2b = g_h2[cb + 1];
        atomicAdd(outb + ((h1a + h2a) & DMASK), cfr[nt][0]);
        atomicAdd(outb + ((h1a + h2b) & DMASK), cfr[nt][1]);
        atomicAdd(outb + ((h1b + h2a) & DMASK), cfr[nt][2]);
        atomicAdd(outb + ((h1b + h2b) & DMASK), cfr[nt][3]);
    }
}

// ---------------------------------------------------------------------------
// Harness entry
// Inputs: bottom1 [32,512,14,14] f32, bottom2 [32,512,14,14] f32,
//         S1 [512,8192] f32, S2 [512,8192] f32.  Output: [32, 8192] f32
// ---------------------------------------------------------------------------
extern "C" void kernel_launch(void* const* d_in, const int* in_sizes, int n_in,
                              void* d_out, int out_size) {
    const float* b1 = (const float*)d_in[0];
    const float* b2 = (const float*)d_in[1];
    const float* S1 = (const float*)d_in[2];
    const float* S2 = (const float*)d_in[3];
    float* out = (float*)d_out;

    cudaFuncSetAttribute(cbp_main, cudaFuncAttributeMaxDynamicSharedMemorySize,
                         SMEM_BYTES);

    cbp_prep<<<dim3(C, 2), 256>>>(S1, S2, out);
    cbp_main<<<dim3(C / TB, C / TB, BATCH), NTHREADS, SMEM_BYTES>>>(b1, b2, out);
}

// round 10
// speedup vs baseline: 1.2481x; 1.2481x over previous
#include <cuda_runtime.h>
#include <cuda_bf16.h>
#include <cstdint>

// Problem constants
#define BATCH 32
#define C     512
#define P     196
#define D     8192
#define DMASK (D - 1)

#define C1B   64           // c1 rows per CTA
#define C2B   64           // c2 chunk (8 chunks)
#define NKS   13           // k-steps of 16 (208 padded)
#define NG    26           // 8-elem groups per row
#define LDB   848          // row stride bytes; 848/16=53 (odd mod 8) -> conflict-free
#define LOOFF 416          // lo region offset within a row (26*16)
#define NTHREADS 256
#define NGRP  (C1B * NG)   // 1664 groups per tile

// Sketch hash/sign tables extracted from the dense S matrices each launch.
__device__ int   g_h1[C];
__device__ int   g_h2[C];
__device__ float g_s1[C];
__device__ float g_s2[C];

// ---------------------------------------------------------------------------
// Kernel 1: extract (h, s) from dense sketch matrices + zero the output.
// grid: (512, 2, 2)  block: 256  (z splits each row for DRAM bandwidth)
// ---------------------------------------------------------------------------
__global__ void cbp_prep(const float* __restrict__ S1, const float* __restrict__ S2,
                         float* __restrict__ out) {
    const int row  = blockIdx.x;
    const int half = blockIdx.z;
    const float4* r = (const float4*)(((blockIdx.y == 0) ? S1 : S2)
                                      + (size_t)row * D + half * (D / 2));
    #pragma unroll
    for (int i = 0; i < (D / 2 / 4) / NTHREADS; i++) {
        int j4 = threadIdx.x + i * NTHREADS;
        float4 v = r[j4];
        float nz = 0.0f; int off = 0;
        if (v.x != 0.0f) { nz = v.x; off = 0; }
        if (v.y != 0.0f) { nz = v.y; off = 1; }
        if (v.z != 0.0f) { nz = v.z; off = 2; }
        if (v.w != 0.0f) { nz = v.w; off = 3; }
        if (nz != 0.0f) {
            int j = half * (D / 2) + j4 * 4 + off;
            if (blockIdx.y == 0) { g_h1[row] = j; g_s1[row] = nz; }
            else                 { g_h2[row] = j; g_s2[row] = nz; }
        }
    }
    int flat = ((blockIdx.z * 2 + blockIdx.y) * 512 + blockIdx.x) * NTHREADS
             + threadIdx.x;
    if (flat < BATCH * D) out[flat] = 0.0f;
}

// ---------------------------------------------------------------------------
// bf16 error-compensated split: 8 elems -> 2 hi words pairs + 2 lo word pairs
// ---------------------------------------------------------------------------
__device__ __forceinline__ void split2(float x0, float x1,
                                       uint32_t& hi, uint32_t& lo) {
    __nv_bfloat16 h0 = __float2bfloat16(x0);
    __nv_bfloat16 h1 = __float2bfloat16(x1);
    __nv_bfloat16 l0 = __float2bfloat16(x0 - __bfloat162float(h0));
    __nv_bfloat16 l1 = __float2bfloat16(x1 - __bfloat162float(h1));
    __nv_bfloat162 hp = __halves2bfloat162(h0, h1);
    __nv_bfloat162 lp = __halves2bfloat162(l0, l1);
    hi = *(uint32_t*)&hp;
    lo = *(uint32_t*)&lp;
}

// Convert 8 sign-folded elems (two float4) -> packed hi uint4 / lo uint4 halves.
__device__ __forceinline__ void cvt_group(float4 va, float4 vb, float s,
                                          uint4& H, uint4& L) {
    split2(va.x * s, va.y * s, H.x, L.x);
    split2(va.z * s, va.w * s, H.y, L.y);
    split2(vb.x * s, vb.y * s, H.z, L.z);
    split2(vb.z * s, vb.w * s, H.w, L.w);
}

// Load one 8-elem group from gmem with tail masking (j8 = 24, 25 partial/pad).
__device__ __forceinline__ void load_group(const float* __restrict__ base,
                                           int row, int j8,
                                           float4& va, float4& vb) {
    const float* p = base + (size_t)row * P + 8 * j8;
    va = (j8 <= 24) ? *(const float4*)p
                    : make_float4(0.f, 0.f, 0.f, 0.f);
    vb = (j8 <= 23) ? *(const float4*)(p + 4)
                    : make_float4(0.f, 0.f, 0.f, 0.f);
}

__device__ __forceinline__ void mma_bf16(float c[4], const uint32_t a[4],
                                         uint32_t b0, uint32_t b1) {
    asm volatile(
        "mma.sync.aligned.m16n8k16.row.col.f32.bf16.bf16.f32 "
        "{%0,%1,%2,%3}, {%4,%5,%6,%7}, {%8,%9}, {%0,%1,%2,%3};"
        : "+f"(c[0]), "+f"(c[1]), "+f"(c[2]), "+f"(c[3])
        : "r"(a[0]), "r"(a[1]), "r"(a[2]), "r"(a[3]), "r"(b0), "r"(b1));
}

__device__ __forceinline__ void ldsm4(uint32_t r[4], uint32_t addr) {
    asm volatile(
        "ldmatrix.sync.aligned.m8n8.x4.shared.b16 {%0,%1,%2,%3}, [%4];"
        : "=r"(r[0]), "=r"(r[1]), "=r"(r[2]), "=r"(r[3]) : "r"(addr));
}

// ---------------------------------------------------------------------------
// Kernel 2: HMMA bf16 3-split Gram + direct REDG scatter.
// grid: (8, 32) = (c1blk, batch); smem 108,544 B -> 2 CTAs/SM.
// 8 warps, 2(m) x 4(n): warp tile 32 rows x 16 cols of the 64x64 chunk.
// Row layout (848B): [26 x 16B hi | 26 x 16B lo | pad]. Conflict-free STS.128
// staging and LDSM (row stride 53*16B, 53 odd mod 8).
// B chunks are converted at prefetch time (packed u32 regs), so the post-
// barrier staging is pure STS.128 and the cvt ALU hides behind MMA/scatter.
// ---------------------------------------------------------------------------
#define SMEM_BYTES (2 * C1B * LDB)

__global__ void __launch_bounds__(NTHREADS, 2)
cbp_main(const float* __restrict__ B1g, const float* __restrict__ B2g,
         float* __restrict__ out) {
    extern __shared__ char smc[];
    char* At = smc;                        // [64][848]: hi | lo
    char* Bt = smc + C1B * LDB;

    const int tid  = threadIdx.x;
    const int wid  = tid >> 5;
    const int lane = tid & 31;
    const int g    = lane >> 2;
    const int tg   = lane & 3;
    const int wm   = wid >> 2;                // 0..1 (32-row half)
    const int wn   = wid & 3;                 // 0..3 (16-col quarter)
    const int b     = blockIdx.y;
    const int c1blk = blockIdx.x * C1B;

    // ---- Stage A (64 x 208 bf16 hi/lo), sign-folded ----
    {
        const float* Ag = B1g + ((size_t)b * C + c1blk) * P;
        for (int idx = tid; idx < NGRP; idx += NTHREADS) {
            int row = idx / NG, j8 = idx % NG;
            float4 va, vb; uint4 H, L;
            load_group(Ag, row, j8, va, vb);
            cvt_group(va, vb, g_s1[c1blk + row], H, L);
            *(uint4*)(At + row * LDB + j8 * 16) = H;
            *(uint4*)(At + row * LDB + LOOFF + j8 * 16) = L;
        }
    }

    // ---- ldmatrix per-lane base addresses ----
    const uint32_t As = (uint32_t)__cvta_generic_to_shared(At);
    const uint32_t Bs = (uint32_t)__cvta_generic_to_shared(Bt);
    const int t  = lane >> 3;                 // tile index 0..3
    const int rr = lane & 7;
    const uint32_t aoff = (uint32_t)(wm * 32 + (t & 1) * 8 + rr) * LDB + (t >> 1) * 16;
    const uint32_t boff = (uint32_t)(wn * 16 + (t >> 1) * 8 + rr) * LDB + (t & 1) * 16;
    const uint32_t aHa = As + aoff, aLa = As + aoff + LOOFF;
    const uint32_t bHa = Bs + boff, bLa = Bs + boff + LOOFF;

    // Preload h1 for this thread's rows
    int h1r[2][2];
    #pragma unroll
    for (int mt = 0; mt < 2; mt++) {
        int r0 = wm * 32 + mt * 16 + g;
        h1r[mt][0] = g_h1[c1blk + r0];
        h1r[mt][1] = g_h1[c1blk + r0 + 8];
    }

    float* outb = out + (size_t)b * D;

    // ---- Prologue: prefetch + convert B chunk 0 ----
    uint4 pfH[7], pfL[7];
    {
        const float* Bg = B2g + (size_t)b * C * P;
        #pragma unroll
        for (int it = 0; it < 7; it++) {
            int idx = tid + it * NTHREADS;
            if (idx < NGRP) {
                int row = idx / NG, j8 = idx % NG;
                float4 va, vb;
                load_group(Bg, row, j8, va, vb);
                cvt_group(va, vb, g_s2[row], pfH[it], pfL[it]);
            }
        }
    }

    for (int cc = 0; cc < C / C2B; cc++) {
        __syncthreads();   // prev chunk's fragment reads of B done (covers A on cc=0)
        // ---- Store prefetched B chunk (pure STS.128, conflict-free) ----
        #pragma unroll
        for (int it = 0; it < 7; it++) {
            int idx = tid + it * NTHREADS;
            if (idx < NGRP) {
                int row = idx / NG, j8 = idx % NG;
                *(uint4*)(Bt + row * LDB + j8 * 16) = pfH[it];
                *(uint4*)(Bt + row * LDB + LOOFF + j8 * 16) = pfL[it];
            }
        }
        __syncthreads();

        // ---- Prefetch + convert next B chunk (hides behind MMA + scatter) ----
        if (cc + 1 < C / C2B) {
            const float* Bg = B2g + ((size_t)b * C + (cc + 1) * C2B) * P;
            const float* sg = g_s2 + (cc + 1) * C2B;
            #pragma unroll
            for (int it = 0; it < 7; it++) {
                int idx = tid + it * NTHREADS;
                if (idx < NGRP) {
                    int row = idx / NG, j8 = idx % NG;
                    float4 va, vb;
                    load_group(Bg, row, j8, va, vb);
                    cvt_group(va, vb, sg[row], pfH[it], pfL[it]);
                }
            }
        }

        // ---- 64x64 tile: warp 32x16, ldmatrix + mma, 3-split accumulation ----
        float cfr[2][2][4];
        #pragma unroll
        for (int mt = 0; mt < 2; mt++)
            #pragma unroll
            for (int nt = 0; nt < 2; nt++)
                #pragma unroll
                for (int q = 0; q < 4; q++) cfr[mt][nt][q] = 0.0f;

        #pragma unroll
        for (int ks = 0; ks < NKS; ks++) {
            const uint32_t kb = ks * 32;      // 16 bf16 hi = 32B per k-step
            uint32_t ah[2][4], al[2][4], bh[4], bl[4];
            ldsm4(ah[0], aHa + kb);
            ldsm4(ah[1], aHa + 16 * LDB + kb);
            ldsm4(al[0], aLa + kb);
            ldsm4(al[1], aLa + 16 * LDB + kb);
            ldsm4(bh, bHa + kb);
            ldsm4(bl, bLa + kb);
            #pragma unroll
            for (int mt = 0; mt < 2; mt++)
                #pragma unroll
                for (int nt = 0; nt < 2; nt++) {
                    mma_bf16(cfr[mt][nt], ah[mt], bh[2 * nt], bh[2 * nt + 1]); // hi*hi
                    mma_bf16(cfr[mt][nt], ah[mt], bl[2 * nt], bl[2 * nt + 1]); // hi*lo
                    mma_bf16(cfr[mt][nt], al[mt], bh[2 * nt], bh[2 * nt + 1]); // lo*hi
                }
        }

        // ---- Scatter C fragments to global bins (fire-and-forget RED.add) ----
        #pragma unroll
        for (int nt = 0; nt < 2; nt++) {
            int cb = cc * C2B + wn * 16 + nt * 8 + 2 * tg;
            int h2a = g_h2[cb];
            int h2b = g_h2[cb + 1];
            #pragma unroll
            for (int mt = 0; mt < 2; mt++) {
                atomicAdd(outb + ((h1r[mt][0] + h2a) & DMASK), cfr[mt][nt][0]);
                atomicAdd(outb + ((h1r[mt][0] + h2b) & DMASK), cfr[mt][nt][1]);
                atomicAdd(outb + ((h1r[mt][1] + h2a) & DMASK), cfr[mt][nt][2]);
                atomicAdd(outb + ((h1r[mt][1] + h2b) & DMASK), cfr[mt][nt][3]);
            }
        }
    }
}

// ---------------------------------------------------------------------------
// Harness entry
// Inputs: bottom1 [32,512,14,14] f32, bottom2 [32,512,14,14] f32,
//         S1 [512,8192] f32, S2 [512,8192] f32.  Output: [32, 8192] f32
// ---------------------------------------------------------------------------
extern "C" void kernel_launch(void* const* d_in, const int* in_sizes, int n_in,
                              void* d_out, int out_size) {
    const float* b1 = (const float*)d_in[0];
    const float* b2 = (const float*)d_in[1];
    const float* S1 = (const float*)d_in[2];
    const float* S2 = (const float*)d_in[3];
    float* out = (float*)d_out;

    cudaFuncSetAttribute(cbp_main, cudaFuncAttributeMaxDynamicSharedMemorySize,
                         SMEM_BYTES);

    cbp_prep<<<dim3(512, 2, 2), NTHREADS>>>(S1, S2, out);
    cbp_main<<<dim3(C / C1B, BATCH), NTHREADS, SMEM_BYTES>>>(b1, b2, out);
}

// round 11
// speedup vs baseline: 1.2799x; 1.0255x over previous
#include <cuda_runtime.h>
#include <cuda_bf16.h>
#include <cstdint>

// Problem constants
#define BATCH 32
#define C     512
#define P     196
#define D     8192
#define DMASK (D - 1)

#define C1B   64           // c1 rows per CTA
#define C2B   64           // c2 chunk (8 chunks)
#define NKS   13           // k-steps of 16 (208 padded)
#define NG    26           // 16B hi groups per row
#define SPROW 832          // scratch row bytes: 416 hi + 416 lo (16B aligned)
#define LDB   848          // smem row stride; 848/16=53 (odd mod 8) -> conflict-free
#define LOOFF 416          // lo region offset within a row
#define NTHREADS 256
#define NCPY  (C1B * 52)   // 16B copies per tile (hi+lo) = 3328

// Sketch hash/sign tables extracted from the dense S matrices each launch.
__device__ int   g_h1[C];
__device__ int   g_h2[C];
__device__ float g_s1[C];
__device__ float g_s2[C];

// Precomputed sign-folded bf16 hi/lo tiles: [2 inputs][32 b][512 c][832 B]
__device__ unsigned char g_split[2u * BATCH * C * SPROW];

// ---------------------------------------------------------------------------
// Kernel 1: extract (h, s) from dense sketch matrices + zero the output.
// grid: (512, 2, 2)  block: 256
// ---------------------------------------------------------------------------
__global__ void cbp_prep(const float* __restrict__ S1, const float* __restrict__ S2,
                         float* __restrict__ out) {
    const int row  = blockIdx.x;
    const int half = blockIdx.z;
    const float4* r = (const float4*)(((blockIdx.y == 0) ? S1 : S2)
                                      + (size_t)row * D + half * (D / 2));
    #pragma unroll
    for (int i = 0; i < (D / 2 / 4) / NTHREADS; i++) {
        int j4 = threadIdx.x + i * NTHREADS;
        float4 v = r[j4];
        float nz = 0.0f; int off = 0;
        if (v.x != 0.0f) { nz = v.x; off = 0; }
        if (v.y != 0.0f) { nz = v.y; off = 1; }
        if (v.z != 0.0f) { nz = v.z; off = 2; }
        if (v.w != 0.0f) { nz = v.w; off = 3; }
        if (nz != 0.0f) {
            int j = half * (D / 2) + j4 * 4 + off;
            if (blockIdx.y == 0) { g_h1[row] = j; g_s1[row] = nz; }
            else                 { g_h2[row] = j; g_s2[row] = nz; }
        }
    }
    int flat = ((blockIdx.z * 2 + blockIdx.y) * 512 + blockIdx.x) * NTHREADS
             + threadIdx.x;
    if (flat < BATCH * D) out[flat] = 0.0f;
}

// ---------------------------------------------------------------------------
// bf16 error-compensated split helpers
// ---------------------------------------------------------------------------
__device__ __forceinline__ void split2(float x0, float x1,
                                       uint32_t& hi, uint32_t& lo) {
    __nv_bfloat16 h0 = __float2bfloat16(x0);
    __nv_bfloat16 h1 = __float2bfloat16(x1);
    __nv_bfloat16 l0 = __float2bfloat16(x0 - __bfloat162float(h0));
    __nv_bfloat16 l1 = __float2bfloat16(x1 - __bfloat162float(h1));
    __nv_bfloat162 hp = __halves2bfloat162(h0, h1);
    __nv_bfloat162 lp = __halves2bfloat162(l0, l1);
    hi = *(uint32_t*)&hp;
    lo = *(uint32_t*)&lp;
}

// ---------------------------------------------------------------------------
// Kernel 2: streaming precompute of the bf16 hi/lo split tiles.
// One task = one 8-elem group of one channel row.  grid: 3328 x 256.
// ---------------------------------------------------------------------------
__global__ void cbp_splitk(const float* __restrict__ B1g,
                           const float* __restrict__ B2g) {
    int task = blockIdx.x * NTHREADS + threadIdx.x;   // < 32768 * 26
    int g   = task % NG;
    int row = task / NG;                              // [inp][b][c] flattened
    int inp = row >> 14;                              // 16384 rows per input
    int rc  = row & 16383;
    int c   = rc & (C - 1);
    const float* src = (inp ? B2g : B1g) + (size_t)rc * P + 8 * g;
    float s = inp ? g_s2[c] : g_s1[c];
    float4 va = (g <= 24) ? *(const float4*)src
                          : make_float4(0.f, 0.f, 0.f, 0.f);
    float4 vb = (g <= 23) ? *(const float4*)(src + 4)
                          : make_float4(0.f, 0.f, 0.f, 0.f);
    uint4 H, L;
    split2(va.x * s, va.y * s, H.x, L.x);
    split2(va.z * s, va.w * s, H.y, L.y);
    split2(vb.x * s, vb.y * s, H.z, L.z);
    split2(vb.z * s, vb.w * s, H.w, L.w);
    unsigned char* dst = g_split + (size_t)row * SPROW;
    *(uint4*)(dst + g * 16) = H;
    *(uint4*)(dst + LOOFF + g * 16) = L;
}

// ---------------------------------------------------------------------------
// MMA / ldmatrix / cp.async helpers
// ---------------------------------------------------------------------------
__device__ __forceinline__ void mma_bf16(float c[4], const uint32_t a[4],
                                         uint32_t b0, uint32_t b1) {
    asm volatile(
        "mma.sync.aligned.m16n8k16.row.col.f32.bf16.bf16.f32 "
        "{%0,%1,%2,%3}, {%4,%5,%6,%7}, {%8,%9}, {%0,%1,%2,%3};"
        : "+f"(c[0]), "+f"(c[1]), "+f"(c[2]), "+f"(c[3])
        : "r"(a[0]), "r"(a[1]), "r"(a[2]), "r"(a[3]), "r"(b0), "r"(b1));
}

__device__ __forceinline__ void ldsm4(uint32_t r[4], uint32_t addr) {
    asm volatile(
        "ldmatrix.sync.aligned.m8n8.x4.shared.b16 {%0,%1,%2,%3}, [%4];"
        : "=r"(r[0]), "=r"(r[1]), "=r"(r[2]), "=r"(r[3]) : "r"(addr));
}

__device__ __forceinline__ void cp16(uint32_t smem_dst, const void* gsrc) {
    asm volatile("cp.async.cg.shared.global [%0], [%1], 16;"
                 :: "r"(smem_dst), "l"(gsrc) : "memory");
}

// ---------------------------------------------------------------------------
// Kernel 3: HMMA bf16 3-split Gram + direct REDG scatter.
// grid: (8, 32) = (c1blk, batch); smem 108,544 B -> 2 CTAs/SM.
// 8 warps, 2(m) x 4(n): warp tile 32 rows x 16 cols of the 64x64 chunk.
// All staging is bare cp.async 16B copies from the precomputed split scratch
// (no conversion, no staging registers).
// ---------------------------------------------------------------------------
#define SMEM_BYTES (2 * C1B * LDB)

__global__ void __launch_bounds__(NTHREADS, 2)
cbp_main(float* __restrict__ out) {
    extern __shared__ char smc[];
    char* At = smc;                        // [64][848]: hi | lo
    char* Bt = smc + C1B * LDB;

    const int tid  = threadIdx.x;
    const int wid  = tid >> 5;
    const int lane = tid & 31;
    const int g    = lane >> 2;
    const int tg   = lane & 3;
    const int wm   = wid >> 2;                // 0..1 (32-row half)
    const int wn   = wid & 3;                 // 0..3 (16-col quarter)
    const int b     = blockIdx.y;
    const int c1blk = blockIdx.x * C1B;

    const uint32_t As = (uint32_t)__cvta_generic_to_shared(At);
    const uint32_t Bs = (uint32_t)__cvta_generic_to_shared(Bt);

    // Per-thread copy slots: 13 copies of 16B each (row = idx/52, j = idx%52)
    int crow[13], cj[13];
    #pragma unroll
    for (int it = 0; it < 13; it++) {
        int idx = tid + it * NTHREADS;
        crow[it] = idx / 52;
        cj[it]   = idx % 52;
    }

    // ---- Stage A tile via cp.async from scratch ----
    {
        const unsigned char* srcA = g_split + ((size_t)b * C + c1blk) * SPROW;
        #pragma unroll
        for (int it = 0; it < 13; it++)
            cp16(As + crow[it] * LDB + cj[it] * 16,
                 srcA + (size_t)crow[it] * SPROW + cj[it] * 16);
        asm volatile("cp.async.commit_group;" ::: "memory");
    }

    // ---- ldmatrix per-lane base addresses ----
    const int t  = lane >> 3;                 // tile index 0..3
    const int rr = lane & 7;
    const uint32_t aoff = (uint32_t)(wm * 32 + (t & 1) * 8 + rr) * LDB + (t >> 1) * 16;
    const uint32_t boff = (uint32_t)(wn * 16 + (t >> 1) * 8 + rr) * LDB + (t & 1) * 16;
    const uint32_t aHa = As + aoff, aLa = As + aoff + LOOFF;
    const uint32_t bHa = Bs + boff, bLa = Bs + boff + LOOFF;

    // Preload h1 for this thread's rows
    int h1r[2][2];
    #pragma unroll
    for (int mt = 0; mt < 2; mt++) {
        int r0 = wm * 32 + mt * 16 + g;
        h1r[mt][0] = g_h1[c1blk + r0];
        h1r[mt][1] = g_h1[c1blk + r0 + 8];
    }

    float* outb = out + (size_t)b * D;
    const unsigned char* srcB0 = g_split
        + ((size_t)BATCH * C + (size_t)b * C) * SPROW;

    for (int cc = 0; cc < C / C2B; cc++) {
        __syncthreads();   // prev chunk's fragment reads of B done
        // ---- Stage B chunk via cp.async ----
        {
            const unsigned char* srcB = srcB0 + (size_t)cc * C2B * SPROW;
            #pragma unroll
            for (int it = 0; it < 13; it++)
                cp16(Bs + crow[it] * LDB + cj[it] * 16,
                     srcB + (size_t)crow[it] * SPROW + cj[it] * 16);
            asm volatile("cp.async.commit_group;" ::: "memory");
            asm volatile("cp.async.wait_group 0;" ::: "memory");
        }
        __syncthreads();   // tiles ready (first iter also covers A)

        // ---- 64x64 tile: warp 32x16, ldmatrix + mma, 3-split accumulation ----
        float cfr[2][2][4];
        #pragma unroll
        for (int mt = 0; mt < 2; mt++)
            #pragma unroll
            for (int nt = 0; nt < 2; nt++)
                #pragma unroll
                for (int q = 0; q < 4; q++) cfr[mt][nt][q] = 0.0f;

        #pragma unroll
        for (int ks = 0; ks < NKS; ks++) {
            const uint32_t kb = ks * 32;      // 16 bf16 = 32B per k-step
            uint32_t ah[2][4], al[2][4], bh[4], bl[4];
            ldsm4(ah[0], aHa + kb);
            ldsm4(ah[1], aHa + 16 * LDB + kb);
            ldsm4(al[0], aLa + kb);
            ldsm4(al[1], aLa + 16 * LDB + kb);
            ldsm4(bh, bHa + kb);
            ldsm4(bl, bLa + kb);
            #pragma unroll
            for (int mt = 0; mt < 2; mt++)
                #pragma unroll
                for (int nt = 0; nt < 2; nt++) {
                    mma_bf16(cfr[mt][nt], ah[mt], bh[2 * nt], bh[2 * nt + 1]); // hi*hi
                    mma_bf16(cfr[mt][nt], ah[mt], bl[2 * nt], bl[2 * nt + 1]); // hi*lo
                    mma_bf16(cfr[mt][nt], al[mt], bh[2 * nt], bh[2 * nt + 1]); // lo*hi
                }
        }

        // ---- Scatter C fragments to global bins (fire-and-forget RED.add) ----
        #pragma unroll
        for (int nt = 0; nt < 2; nt++) {
            int cb = cc * C2B + wn * 16 + nt * 8 + 2 * tg;
            int h2a = g_h2[cb];
            int h2b = g_h2[cb + 1];
            #pragma unroll
            for (int mt = 0; mt < 2; mt++) {
                atomicAdd(outb + ((h1r[mt][0] + h2a) & DMASK), cfr[mt][nt][0]);
                atomicAdd(outb + ((h1r[mt][0] + h2b) & DMASK), cfr[mt][nt][1]);
                atomicAdd(outb + ((h1r[mt][1] + h2a) & DMASK), cfr[mt][nt][2]);
                atomicAdd(outb + ((h1r[mt][1] + h2b) & DMASK), cfr[mt][nt][3]);
            }
        }
    }
}

// ---------------------------------------------------------------------------
// Harness entry
// Inputs: bottom1 [32,512,14,14] f32, bottom2 [32,512,14,14] f32,
//         S1 [512,8192] f32, S2 [512,8192] f32.  Output: [32, 8192] f32
// ---------------------------------------------------------------------------
extern "C" void kernel_launch(void* const* d_in, const int* in_sizes, int n_in,
                              void* d_out, int out_size) {
    const float* b1 = (const float*)d_in[0];
    const float* b2 = (const float*)d_in[1];
    const float* S1 = (const float*)d_in[2];
    const float* S2 = (const float*)d_in[3];
    float* out = (float*)d_out;

    cudaFuncSetAttribute(cbp_main, cudaFuncAttributeMaxDynamicSharedMemorySize,
                         SMEM_BYTES);

    cbp_prep<<<dim3(512, 2, 2), NTHREADS>>>(S1, S2, out);
    cbp_splitk<<<(2 * BATCH * C * NG) / NTHREADS, NTHREADS>>>(b1, b2);
    cbp_main<<<dim3(C / C1B, BATCH), NTHREADS, SMEM_BYTES>>>(out);
}

// round 12
// speedup vs baseline: 1.3491x; 1.0541x over previous
#include <cuda_runtime.h>
#include <cuda_bf16.h>
#include <cstdint>

// Problem constants
#define BATCH 32
#define C     512
#define P     196
#define D     8192
#define DMASK (D - 1)

#define C1B   64           // c1 rows per CTA
#define C2B   64           // c2 chunk (8 chunks)
#define NKS   13           // k-steps of 16 (208 padded)
#define NG    26           // 16B hi groups per row
#define SPROW 832          // scratch row bytes: 416 hi + 416 lo
#define LDB   848          // smem row stride; 848/16=53 (odd mod 8) -> conflict-free
#define LOOFF 416          // lo region offset within a row
#define NTHREADS 256

#define PREP_BLKS  2048    // S-scan + out-zero blocks
#define SPLIT_BLKS 3328    // bf16-split blocks (2*32*512*26/256)

// Hash/sign tables (orig channel order) + sorted-permutation tables.
__device__ int   g_h1[C];
__device__ int   g_h2[C];
__device__ float g_s1[C];
__device__ float g_s2[C];
__device__ int   g_p1[C],  g_p2[C];    // sorted idx -> orig channel
__device__ int   g_h1s[C], g_h2s[C];   // h sorted ascending
__device__ float g_s1s[C], g_s2s[C];   // s in sorted order

// Precomputed (unsigned-sign, raw x) bf16 hi/lo tiles: [2][32 b][512 c][832 B]
__device__ unsigned char g_split[2u * BATCH * C * SPROW];

// ---------------------------------------------------------------------------
// bf16 error-compensated split helpers
// ---------------------------------------------------------------------------
__device__ __forceinline__ void split2(float x0, float x1,
                                       uint32_t& hi, uint32_t& lo) {
    __nv_bfloat16 h0 = __float2bfloat16(x0);
    __nv_bfloat16 h1 = __float2bfloat16(x1);
    __nv_bfloat16 l0 = __float2bfloat16(x0 - __bfloat162float(h0));
    __nv_bfloat16 l1 = __float2bfloat16(x1 - __bfloat162float(h1));
    __nv_bfloat162 hp = __halves2bfloat162(h0, h1);
    __nv_bfloat162 lp = __halves2bfloat162(l0, l1);
    hi = *(uint32_t*)&hp;
    lo = *(uint32_t*)&lp;
}

// ---------------------------------------------------------------------------
// Kernel 1 (merged): S-matrix (h,s) extraction + out-zeroing  ||  bf16 split
// of raw bottom data (sign applied later at scatter). The two halves are
// independent, so they overlap inside one launch.  grid: 5376 x 256
// ---------------------------------------------------------------------------
__global__ void cbp_prep(const float* __restrict__ S1, const float* __restrict__ S2,
                         const float* __restrict__ B1g, const float* __restrict__ B2g,
                         float* __restrict__ out) {
    const int bx = blockIdx.x;
    if (bx < PREP_BLKS) {
        // ---- S scan: 512 rows x 2 matrices x 2 halves ----
        const int row  = bx & 511;
        const int y    = (bx >> 9) & 1;
        const int half = bx >> 10;
        const float4* r = (const float4*)(((y == 0) ? S1 : S2)
                                          + (size_t)row * D + half * (D / 2));
        #pragma unroll
        for (int i = 0; i < (D / 2 / 4) / NTHREADS; i++) {
            int j4 = threadIdx.x + i * NTHREADS;
            float4 v = r[j4];
            float nz = 0.0f; int off = 0;
            if (v.x != 0.0f) { nz = v.x; off = 0; }
            if (v.y != 0.0f) { nz = v.y; off = 1; }
            if (v.z != 0.0f) { nz = v.z; off = 2; }
            if (v.w != 0.0f) { nz = v.w; off = 3; }
            if (nz != 0.0f) {
                int j = half * (D / 2) + j4 * 4 + off;
                if (y == 0) { g_h1[row] = j; g_s1[row] = nz; }
                else        { g_h2[row] = j; g_s2[row] = nz; }
            }
        }
        int flat = bx * NTHREADS + threadIdx.x;
        if (flat < BATCH * D) out[flat] = 0.0f;
    } else {
        // ---- bf16 hi/lo split of raw bottoms ----
        int task = (bx - PREP_BLKS) * NTHREADS + threadIdx.x;
        int g   = task % NG;
        int row = task / NG;                  // [inp][b][c] flattened
        int inp = row >> 14;
        int rc  = row & 16383;
        const float* src = (inp ? B2g : B1g) + (size_t)rc * P + 8 * g;
        float4 va = (g <= 24) ? *(const float4*)src
                              : make_float4(0.f, 0.f, 0.f, 0.f);
        float4 vb = (g <= 23) ? *(const float4*)(src + 4)
                              : make_float4(0.f, 0.f, 0.f, 0.f);
        uint4 H, L;
        split2(va.x, va.y, H.x, L.x);
        split2(va.z, va.w, H.y, L.y);
        split2(vb.x, vb.y, H.z, L.z);
        split2(vb.z, vb.w, H.w, L.w);
        unsigned char* dst = g_split + (size_t)row * SPROW;
        *(uint4*)(dst + g * 16) = H;
        *(uint4*)(dst + LOOFF + g * 16) = L;
    }
}

// ---------------------------------------------------------------------------
// Kernel 2: sort channels by hash (rank sort, 512 threads per block).
// block 0: (h1, s1) -> p1/h1s/s1s;  block 1: (h2, s2).
// Sorted order clusters scatter addresses within each warp-RED instruction.
// ---------------------------------------------------------------------------
__global__ void cbp_sort() {
    __shared__ int hh[C];
    const int tid = threadIdx.x;
    int*   h = blockIdx.x ? g_h2  : g_h1;
    float* s = blockIdx.x ? g_s2  : g_s1;
    int*   p = blockIdx.x ? g_p2  : g_p1;
    int*   hs = blockIdx.x ? g_h2s : g_h1s;
    float* ss = blockIdx.x ? g_s2s : g_s1s;
    hh[tid] = h[tid];
    __syncthreads();
    int mine = hh[tid];
    int rank = 0;
    for (int j = 0; j < C; j++) {
        int hj = hh[j];
        rank += (hj < mine) || (hj == mine && j < tid);
    }
    p[rank]  = tid;
    hs[rank] = mine;
    ss[rank] = s[tid];
}

// ---------------------------------------------------------------------------
// MMA / ldmatrix / cp.async helpers
// ---------------------------------------------------------------------------
__device__ __forceinline__ void mma_bf16(float c[4], const uint32_t a[4],
                                         uint32_t b0, uint32_t b1) {
    asm volatile(
        "mma.sync.aligned.m16n8k16.row.col.f32.bf16.bf16.f32 "
        "{%0,%1,%2,%3}, {%4,%5,%6,%7}, {%8,%9}, {%0,%1,%2,%3};"
        : "+f"(c[0]), "+f"(c[1]), "+f"(c[2]), "+f"(c[3])
        : "r"(a[0]), "r"(a[1]), "r"(a[2]), "r"(a[3]), "r"(b0), "r"(b1));
}

__device__ __forceinline__ void ldsm4(uint32_t r[4], uint32_t addr) {
    asm volatile(
        "ldmatrix.sync.aligned.m8n8.x4.shared.b16 {%0,%1,%2,%3}, [%4];"
        : "=r"(r[0]), "=r"(r[1]), "=r"(r[2]), "=r"(r[3]) : "r"(addr));
}

__device__ __forceinline__ void cp16(uint32_t smem_dst, const void* gsrc) {
    asm volatile("cp.async.cg.shared.global [%0], [%1], 16;"
                 :: "r"(smem_dst), "l"(gsrc) : "memory");
}

// ---------------------------------------------------------------------------
// Kernel 3: HMMA bf16 3-split Gram over hash-sorted channels + REDG scatter.
// grid: (8, 32) = (c1blk, batch); smem 108,544 B -> 2 CTAs/SM.
// 8 warps, 2(m) x 4(n).  Tiles staged (via perm) with cp.async from scratch.
// Scatter: all 32 lanes of one RED span ~256 sorted bins -> ~8 L2 lines.
// ---------------------------------------------------------------------------
#define SMEM_BYTES (2 * C1B * LDB)

__global__ void __launch_bounds__(NTHREADS, 2)
cbp_main(float* __restrict__ out) {
    extern __shared__ char smc[];
    char* At = smc;                        // [64][848]: hi | lo
    char* Bt = smc + C1B * LDB;

    const int tid  = threadIdx.x;
    const int wid  = tid >> 5;
    const int lane = tid & 31;
    const int g    = lane >> 2;
    const int tg   = lane & 3;
    const int wm   = wid >> 2;                // 0..1 (32-row half)
    const int wn   = wid & 3;                 // 0..3 (16-col quarter)
    const int b     = blockIdx.y;
    const int c1blk = blockIdx.x * C1B;       // index in SORTED c1 domain

    const uint32_t As = (uint32_t)__cvta_generic_to_shared(At);
    const uint32_t Bs = (uint32_t)__cvta_generic_to_shared(Bt);

    // Per-thread copy slots: 13 x 16B (row = idx/52, j = idx%52)
    int crow[13], cj[13];
    #pragma unroll
    for (int it = 0; it < 13; it++) {
        int idx = tid + it * NTHREADS;
        crow[it] = idx / 52;
        cj[it]   = idx % 52;
    }

    // ---- Stage A tile via cp.async (rows permuted by sorted h1) ----
    {
        const unsigned char* baseA = g_split + (size_t)b * C * SPROW;
        #pragma unroll
        for (int it = 0; it < 13; it++) {
            int orig = __ldg(g_p1 + c1blk + crow[it]);
            cp16(As + crow[it] * LDB + cj[it] * 16,
                 baseA + (size_t)orig * SPROW + cj[it] * 16);
        }
        asm volatile("cp.async.commit_group;" ::: "memory");
    }

    // ---- ldmatrix per-lane base addresses ----
    const int t  = lane >> 3;
    const int rr = lane & 7;
    const uint32_t aoff = (uint32_t)(wm * 32 + (t & 1) * 8 + rr) * LDB + (t >> 1) * 16;
    const uint32_t boff = (uint32_t)(wn * 16 + (t >> 1) * 8 + rr) * LDB + (t & 1) * 16;
    const uint32_t aHa = As + aoff, aLa = As + aoff + LOOFF;
    const uint32_t bHa = Bs + boff, bLa = Bs + boff + LOOFF;

    // Preload sorted h1 + s1 for this thread's rows
    int   h1r[2][2];
    float s1r[2][2];
    #pragma unroll
    for (int mt = 0; mt < 2; mt++) {
        int r0 = c1blk + wm * 32 + mt * 16 + g;
        h1r[mt][0] = g_h1s[r0];      h1r[mt][1] = g_h1s[r0 + 8];
        s1r[mt][0] = g_s1s[r0];      s1r[mt][1] = g_s1s[r0 + 8];
    }

    float* outb = out + (size_t)b * D;
    const unsigned char* baseB = g_split + ((size_t)BATCH * C + (size_t)b * C) * SPROW;

    for (int cc = 0; cc < C / C2B; cc++) {
        __syncthreads();   // prev chunk's fragment reads of B done
        // ---- Stage B chunk via cp.async (rows permuted by sorted h2) ----
        {
            #pragma unroll
            for (int it = 0; it < 13; it++) {
                int orig = __ldg(g_p2 + cc * C2B + crow[it]);
                cp16(Bs + crow[it] * LDB + cj[it] * 16,
                     baseB + (size_t)orig * SPROW + cj[it] * 16);
            }
            asm volatile("cp.async.commit_group;" ::: "memory");
            asm volatile("cp.async.wait_group 0;" ::: "memory");
        }
        __syncthreads();   // tiles ready (first iter also covers A)

        // ---- 64x64 tile: warp 32x16, ldmatrix + mma, 3-split accumulation ----
        float cfr[2][2][4];
        #pragma unroll
        for (int mt = 0; mt < 2; mt++)
            #pragma unroll
            for (int nt = 0; nt < 2; nt++)
                #pragma unroll
                for (int q = 0; q < 4; q++) cfr[mt][nt][q] = 0.0f;

        #pragma unroll
        for (int ks = 0; ks < NKS; ks++) {
            const uint32_t kb = ks * 32;
            uint32_t ah[2][4], al[2][4], bh[4], bl[4];
            ldsm4(ah[0], aHa + kb);
            ldsm4(ah[1], aHa + 16 * LDB + kb);
            ldsm4(al[0], aLa + kb);
            ldsm4(al[1], aLa + 16 * LDB + kb);
            ldsm4(bh, bHa + kb);
            ldsm4(bl, bLa + kb);
            #pragma unroll
            for (int mt = 0; mt < 2; mt++)
                #pragma unroll
                for (int nt = 0; nt < 2; nt++) {
                    mma_bf16(cfr[mt][nt], ah[mt], bh[2 * nt], bh[2 * nt + 1]); // hi*hi
                    mma_bf16(cfr[mt][nt], ah[mt], bl[2 * nt], bl[2 * nt + 1]); // hi*lo
                    mma_bf16(cfr[mt][nt], al[mt], bh[2 * nt], bh[2 * nt + 1]); // lo*hi
                }
        }

        // ---- Scatter with sign weights (bins clustered by sort) ----
        #pragma unroll
        for (int nt = 0; nt < 2; nt++) {
            int cb = cc * C2B + wn * 16 + nt * 8 + 2 * tg;
            int   h2a = __ldg(g_h2s + cb),  h2b = __ldg(g_h2s + cb + 1);
            float s2a = __ldg(g_s2s + cb),  s2b = __ldg(g_s2s + cb + 1);
            #pragma unroll
            for (int mt = 0; mt < 2; mt++) {
                atomicAdd(outb + ((h1r[mt][0] + h2a) & DMASK),
                          cfr[mt][nt][0] * (s1r[mt][0] * s2a));
                atomicAdd(outb + ((h1r[mt][0] + h2b) & DMASK),
                          cfr[mt][nt][1] * (s1r[mt][0] * s2b));
                atomicAdd(outb + ((h1r[mt][1] + h2a) & DMASK),
                          cfr[mt][nt][2] * (s1r[mt][1] * s2a));
                atomicAdd(outb + ((h1r[mt][1] + h2b) & DMASK),
                          cfr[mt][nt][3] * (s1r[mt][1] * s2b));
            }
        }
    }
}

// ---------------------------------------------------------------------------
// Harness entry
// Inputs: bottom1 [32,512,14,14] f32, bottom2 [32,512,14,14] f32,
//         S1 [512,8192] f32, S2 [512,8192] f32.  Output: [32, 8192] f32
// ---------------------------------------------------------------------------
extern "C" void kernel_launch(void* const* d_in, const int* in_sizes, int n_in,
                              void* d_out, int out_size) {
    const float* b1 = (const float*)d_in[0];
    const float* b2 = (const float*)d_in[1];
    const float* S1 = (const float*)d_in[2];
    const float* S2 = (const float*)d_in[3];
    float* out = (float*)d_out;

    cudaFuncSetAttribute(cbp_main, cudaFuncAttributeMaxDynamicSharedMemorySize,
                         SMEM_BYTES);

    cbp_prep<<<PREP_BLKS + SPLIT_BLKS, NTHREADS>>>(S1, S2, b1, b2, out);
    cbp_sort<<<2, C>>>();
    cbp_main<<<dim3(C / C1B, BATCH), NTHREADS, SMEM_BYTES>>>(out);
}